// round 2
// baseline (speedup 1.0000x reference)
#include <cuda_runtime.h>
#include <math.h>

#define NN 100000
#define MM 800000
#define HH 128
#define NCC 1000
#define CC 1024
#define NLAYERS 4
#define EPSL 1e-5f

// ---- scratch (static __device__ per harness rules) ----
__device__ float d_h0[NN * HH];
__device__ float d_h1[NN * HH];
__device__ float d_agg[NN * HH];
__device__ float d_deg[NN];
__device__ float d_invdeg[NN];
__device__ float d_base[NCC * HH];
__device__ float d_P[(size_t)NCC * HH * CC];   // layout [nc][k][c], c contiguous
__device__ float d_cfge[CC * HH];
__device__ float d_gsum[HH];

__device__ __forceinline__ float gelu_f(float x) {
    return 0.5f * x * (1.0f + erff(x * 0.70710678118654752440f));
}

// ---------------- zero helpers (reference globals directly) ----------------
__global__ void zero_selected(int which) {
    size_t n;
    float* p;
    if (which == 0) { p = d_agg;  n = (size_t)NN * HH; }
    else if (which == 1) { p = d_deg; n = NN; }
    else if (which == 2) { p = d_gsum; n = HH; }
    else { p = d_cfge; n = (size_t)CC * HH; }
    for (size_t i = (size_t)blockIdx.x * blockDim.x + threadIdx.x; i < n;
         i += (size_t)gridDim.x * blockDim.x)
        p[i] = 0.0f;
}

// ---------------- degree ----------------
__global__ void degree_kernel(const int* __restrict__ ei) {
    int e = blockIdx.x * 256 + threadIdx.x;
    if (e < MM) atomicAdd(&d_deg[ei[MM + e]], 1.0f);
}
__global__ void invdeg_kernel() {
    int n = blockIdx.x * 256 + threadIdx.x;
    if (n < NN) d_invdeg[n] = 1.0f / fmaxf(d_deg[n], 1.0f);
}

// ---------------- input embed + proj + LN + gelu ----------------
// 4 nodes per block, 128 threads (thread = output column k)
__global__ __launch_bounds__(128) void input_kernel(
    const float* __restrict__ nf, const int* __restrict__ opc,
    const float* __restrict__ depth, const float* __restrict__ emb,
    const float* __restrict__ w, const float* __restrict__ b,
    const float* __restrict__ g, const float* __restrict__ beta)
{
    __shared__ __align__(16) float xs[4 * 208];
    __shared__ float red[8];
    int tid = threadIdx.x;
    int n0 = blockIdx.x * 4;
    for (int i = 0; i < 4; i++) {
        int n = n0 + i;
        for (int d = tid; d < 140; d += 128) xs[i * 208 + d] = nf[n * 140 + d];
        int oc = opc[n]; oc = oc < 0 ? 0 : (oc > 119 ? 119 : oc);
        if (tid < 64) xs[i * 208 + 140 + tid] = emb[oc * 64 + tid];
        if (tid == 0) {
            xs[i * 208 + 204] = depth[n];
            xs[i * 208 + 205] = 0.f; xs[i * 208 + 206] = 0.f; xs[i * 208 + 207] = 0.f;
        }
    }
    __syncthreads();
    int k = tid;
    float acc[4];
    float bb = b[k];
#pragma unroll
    for (int i = 0; i < 4; i++) acc[i] = bb;
    for (int d = 0; d < 204; d += 4) {
        float w0 = w[(d + 0) * 128 + k];
        float w1 = w[(d + 1) * 128 + k];
        float w2 = w[(d + 2) * 128 + k];
        float w3 = w[(d + 3) * 128 + k];
#pragma unroll
        for (int i = 0; i < 4; i++) {
            float4 a = *(const float4*)&xs[i * 208 + d];
            acc[i] += a.x * w0 + a.y * w1 + a.z * w2 + a.w * w3;
        }
    }
    {
        float wv = w[204 * 128 + k];
#pragma unroll
        for (int i = 0; i < 4; i++) acc[i] += xs[i * 208 + 204] * wv;
    }
    float gk = g[k], bk = beta[k];
    for (int i = 0; i < 4; i++) {
        float v = acc[i];
        float s = v, s2 = v * v;
        for (int o = 16; o > 0; o >>= 1) {
            s += __shfl_down_sync(0xffffffffu, s, o);
            s2 += __shfl_down_sync(0xffffffffu, s2, o);
        }
        if ((tid & 31) == 0) { red[tid >> 5] = s; red[4 + (tid >> 5)] = s2; }
        __syncthreads();
        float mu = (red[0] + red[1] + red[2] + red[3]) * (1.0f / 128.0f);
        float ms = (red[4] + red[5] + red[6] + red[7]) * (1.0f / 128.0f);
        float r = rsqrtf(ms - mu * mu + EPSL);
        float ln = (v - mu) * r * gk + bk;
        d_h0[(n0 + i) * 128 + k] = gelu_f(ln);
        __syncthreads();
    }
}

// ---------------- edge scatter (mean aggregation numerator) ----------------
__global__ __launch_bounds__(256) void scatter_kernel(const int* __restrict__ ei, int flip) {
    const float* hin = flip ? d_h1 : d_h0;
    int gid = blockIdx.x * 256 + threadIdx.x;
    int e = gid >> 5;
    if (e >= MM) return;
    int lane = gid & 31;
    int s = ei[e], d = ei[MM + e];
    float4 v = ((const float4*)(hin + (size_t)s * 128))[lane];
    float* dst = d_agg + (size_t)d * 128 + lane * 4;
    atomicAdd(dst + 0, v.x);
    atomicAdd(dst + 1, v.y);
    atomicAdd(dst + 2, v.z);
    atomicAdd(dst + 3, v.w);
}

// ---------------- SAGE conv + residual + LN ----------------
// 8 nodes per block, 128 threads (thread = output column k)
__global__ __launch_bounds__(128) void conv_kernel(
    int flip, const float* __restrict__ Wl, const float* __restrict__ bl,
    const float* __restrict__ Wr, const float* __restrict__ lg,
    const float* __restrict__ lb)
{
    const float* hin = flip ? d_h1 : d_h0;
    float* hout = flip ? d_h0 : d_h1;
    __shared__ __align__(16) float ash[8 * 256];
    __shared__ float red[8];
    int tid = threadIdx.x;
    int n0 = blockIdx.x * 8;
    for (int idx = tid; idx < 8 * 256; idx += 128) {
        int i = idx >> 8, d = idx & 255;
        int n = n0 + i;
        ash[idx] = (d < 128) ? d_agg[(size_t)n * 128 + d] * d_invdeg[n]
                             : hin[(size_t)n * 128 + (d - 128)];
    }
    __syncthreads();
    int k = tid;
    float acc[8];
#pragma unroll
    for (int i = 0; i < 8; i++) acc[i] = 0.0f;
    for (int d = 0; d < 128; d += 4) {
        float w0 = Wl[(d + 0) * 128 + k];
        float w1 = Wl[(d + 1) * 128 + k];
        float w2 = Wl[(d + 2) * 128 + k];
        float w3 = Wl[(d + 3) * 128 + k];
#pragma unroll
        for (int i = 0; i < 8; i++) {
            float4 a = *(const float4*)&ash[i * 256 + d];
            acc[i] += a.x * w0 + a.y * w1 + a.z * w2 + a.w * w3;
        }
    }
    for (int d = 0; d < 128; d += 4) {
        float w0 = Wr[(d + 0) * 128 + k];
        float w1 = Wr[(d + 1) * 128 + k];
        float w2 = Wr[(d + 2) * 128 + k];
        float w3 = Wr[(d + 3) * 128 + k];
#pragma unroll
        for (int i = 0; i < 8; i++) {
            float4 a = *(const float4*)&ash[i * 256 + 128 + d];
            acc[i] += a.x * w0 + a.y * w1 + a.z * w2 + a.w * w3;
        }
    }
    float bias = bl[k], gk = lg[k], bk = lb[k];
    for (int i = 0; i < 8; i++) {
        float gv = ash[i * 256 + 128 + k] + gelu_f(acc[i] + bias);
        float s = gv, s2 = gv * gv;
        for (int o = 16; o > 0; o >>= 1) {
            s += __shfl_down_sync(0xffffffffu, s, o);
            s2 += __shfl_down_sync(0xffffffffu, s2, o);
        }
        if ((tid & 31) == 0) { red[tid >> 5] = s; red[4 + (tid >> 5)] = s2; }
        __syncthreads();
        float mu = (red[0] + red[1] + red[2] + red[3]) * (1.0f / 128.0f);
        float ms = (red[4] + red[5] + red[6] + red[7]) * (1.0f / 128.0f);
        float r = rsqrtf(ms - mu * mu + EPSL);
        hout[(size_t)(n0 + i) * 128 + k] = (gv - mu) * r * gk + bk;
        __syncthreads();
    }
}

// ---------------- global mean partials (final h lives in d_h0) -------------
__global__ __launch_bounds__(128) void gsum_kernel() {
    int k = threadIdx.x;
    float s = 0.0f;
    for (int n = blockIdx.x; n < NN; n += gridDim.x) s += d_h0[(size_t)n * 128 + k];
    atomicAdd(&d_gsum[k], s);
}

// ---------------- base[nc] = h[config_ids[nc]] @ cfg_w[:128] + cfg_b -------
__global__ __launch_bounds__(128) void base_kernel(
    const int* __restrict__ cid, const float* __restrict__ cw,
    const float* __restrict__ cb)
{
    __shared__ float hs[128];
    int nc = blockIdx.x, k = threadIdx.x;
    int node = cid[nc];
    hs[k] = d_h0[(size_t)node * 128 + k];
    __syncthreads();
    float a = cb[k];
    for (int d = 0; d < 128; d++) a += hs[d] * cw[d * 128 + k];
    d_base[nc * 128 + k] = a;
}

// ---------------- proj (18-wide) + SE, store transposed into d_P -----------
// grid: (32 c-tiles, 1000 nc); block 128
__global__ __launch_bounds__(128) void projse_kernel(
    const float* __restrict__ cf, const float* __restrict__ cw,
    const float* __restrict__ w1, const float* __restrict__ b1,
    const float* __restrict__ w2, const float* __restrict__ b2)
{
    __shared__ float bs[128];
    __shared__ float cws[18 * 128];
    __shared__ float w1s[128 * 16];
    __shared__ float w2s[16 * 128];
    __shared__ float b1s[16], b2s[128];
    __shared__ float vsh[18];
    __shared__ float psh[128];
    __shared__ float rpart[16 * 8];
    __shared__ float rsh[16];
    __shared__ float tile[128 * 33];
    int tid = threadIdx.x;
    int nc = blockIdx.y;
    int c0 = blockIdx.x * 32;
    bs[tid] = d_base[nc * 128 + tid];
    b2s[tid] = b2[tid];
    if (tid < 16) b1s[tid] = b1[tid];
    for (int i = tid; i < 18 * 128; i += 128) cws[i] = cw[128 * 128 + i];
    for (int i = tid; i < 128 * 16; i += 128) w1s[i] = w1[i];
    for (int i = tid; i < 16 * 128; i += 128) w2s[i] = w2[i];
    __syncthreads();
    int k = tid;
    for (int ci = 0; ci < 32; ci++) {
        int c = c0 + ci;
        if (tid < 18) vsh[tid] = cf[((size_t)c * NCC + nc) * 18 + tid];
        __syncthreads();
        float t = bs[k];
#pragma unroll
        for (int d = 0; d < 18; d++) t += vsh[d] * cws[d * 128 + k];
        float p = gelu_f(t);
        psh[k] = p;
        __syncthreads();
        {
            int j = tid & 15, gg = tid >> 4;
            float part = 0.0f;
#pragma unroll
            for (int q = 0; q < 16; q++) {
                int kk = gg * 16 + q;
                part += psh[kk] * w1s[kk * 16 + j];
            }
            rpart[j * 8 + gg] = part;
        }
        __syncthreads();
        if (tid < 16) {
            float r = b1s[tid];
#pragma unroll
            for (int gg = 0; gg < 8; gg++) r += rpart[tid * 8 + gg];
            rsh[tid] = fmaxf(r, 0.0f);
        }
        __syncthreads();
        float sv = b2s[k];
#pragma unroll
        for (int j = 0; j < 16; j++) sv += rsh[j] * w2s[j * 128 + k];
        float sig = 1.0f / (1.0f + expf(-sv));
        tile[k * 33 + ci] = p * sig;
        __syncthreads();
    }
    for (int idx = tid; idx < 128 * 32; idx += 128) {
        int kk = idx >> 5, j = idx & 31;
        d_P[(size_t)nc * (HH * CC) + (size_t)kk * CC + c0 + j] = tile[kk * 33 + j];
    }
}

// ---------------- chunked softmax over configs + mean over nc --------------
// grid: (128 k, 25 nc-groups of 40); block 512 (thread = c within chunk)
__global__ __launch_bounds__(512) void softmax_kernel(const float* __restrict__ temp) {
    __shared__ float sbuf[16];
    int tid = threadIdx.x;
    int k = blockIdx.x;
    int grp = blockIdx.y;
    float invT = 1.0f / temp[0];
    float acc0 = 0.0f, acc1 = 0.0f;
    for (int nc = grp * 40; nc < grp * 40 + 40; nc++) {
        size_t rb = (size_t)nc * (HH * CC) + (size_t)k * CC;
#pragma unroll
        for (int c2 = 0; c2 < 2; c2++) {
            float x = d_P[rb + c2 * 512 + tid];
            float y = x * invT;
            float m = y;
            for (int o = 16; o > 0; o >>= 1) m = fmaxf(m, __shfl_xor_sync(0xffffffffu, m, o));
            if ((tid & 31) == 0) sbuf[tid >> 5] = m;
            __syncthreads();
            m = sbuf[0];
#pragma unroll
            for (int w = 1; w < 16; w++) m = fmaxf(m, sbuf[w]);
            __syncthreads();
            float e = expf(y - m);
            float s = e;
            for (int o = 16; o > 0; o >>= 1) s += __shfl_xor_sync(0xffffffffu, s, o);
            if ((tid & 31) == 0) sbuf[tid >> 5] = s;
            __syncthreads();
            s = 0.0f;
#pragma unroll
            for (int w = 0; w < 16; w++) s += sbuf[w];
            __syncthreads();
            float contrib = x * (e / s);
            if (c2 == 0) acc0 += contrib; else acc1 += contrib;
        }
    }
    atomicAdd(&d_cfge[(0 * 512 + tid) * 128 + k], acc0 * (1.0f / (float)NCC));
    atomicAdd(&d_cfge[(512 + tid) * 128 + k], acc1 * (1.0f / (float)NCC));
}

// ---------------- scoring head ----------------
__global__ __launch_bounds__(128) void head_kernel(
    const float* __restrict__ w1, const float* __restrict__ b1v,
    const float* __restrict__ w2, const float* __restrict__ b2v,
    const float* __restrict__ w3, const float* __restrict__ b3v,
    float* __restrict__ out)
{
    __shared__ float fin[256];
    __shared__ float x1[128];
    __shared__ float x2[64];
    int tid = threadIdx.x;
    int c = blockIdx.x;
    fin[tid] = d_gsum[tid] * (1.0f / (float)NN);
    fin[128 + tid] = d_cfge[c * 128 + tid];
    __syncthreads();
    float a = b1v[tid];
    for (int d = 0; d < 256; d++) a += fin[d] * w1[d * 128 + tid];
    x1[tid] = gelu_f(a);
    __syncthreads();
    if (tid < 64) {
        float a2 = b2v[tid];
        for (int d = 0; d < 128; d++) a2 += x1[d] * w2[d * 64 + tid];
        x2[tid] = gelu_f(a2);
    }
    __syncthreads();
    if (tid == 0) {
        float s = b3v[0];
        for (int d = 0; d < 64; d++) s += x2[d] * w3[d];
        out[c] = s;
    }
}

extern "C" void kernel_launch(void* const* d_in, const int* in_sizes, int n_in,
                              void* d_out, int out_size) {
    const float* node_feat     = (const float*)d_in[0];
    const int*   node_opcode   = (const int*)  d_in[1];
    const float* topo_depth    = (const float*)d_in[2];
    const int*   edge_index    = (const int*)  d_in[3];
    const int*   config_ids    = (const int*)  d_in[4];
    const float* config_feat   = (const float*)d_in[5];
    const float* temperature   = (const float*)d_in[6];
    const float* opcode_embed  = (const float*)d_in[7];
    const float* in_w          = (const float*)d_in[8];
    const float* in_b          = (const float*)d_in[9];
    const float* in_g          = (const float*)d_in[10];
    const float* in_beta       = (const float*)d_in[11];
    const float* sage_Wl       = (const float*)d_in[12];
    const float* sage_bl       = (const float*)d_in[13];
    const float* sage_Wr       = (const float*)d_in[14];
    const float* ln_g          = (const float*)d_in[15];
    const float* ln_b          = (const float*)d_in[16];
    const float* cfg_w         = (const float*)d_in[17];
    const float* cfg_b         = (const float*)d_in[18];
    const float* se_w1         = (const float*)d_in[19];
    const float* se_b1         = (const float*)d_in[20];
    const float* se_w2         = (const float*)d_in[21];
    const float* se_b2         = (const float*)d_in[22];
    const float* h_w1          = (const float*)d_in[23];
    const float* h_b1          = (const float*)d_in[24];
    const float* h_w2          = (const float*)d_in[25];
    const float* h_b2          = (const float*)d_in[26];
    const float* h_w3          = (const float*)d_in[27];
    const float* h_b3          = (const float*)d_in[28];
    float* out = (float*)d_out;

    // degree -> inv_deg
    zero_selected<<<400, 256>>>(1);
    degree_kernel<<<(MM + 255) / 256, 256>>>(edge_index);
    invdeg_kernel<<<(NN + 255) / 256, 256>>>();

    // input embedding + projection
    input_kernel<<<NN / 4, 128>>>(node_feat, node_opcode, topo_depth, opcode_embed,
                                  in_w, in_b, in_g, in_beta);

    // 4 SAGE layers
    for (int l = 0; l < NLAYERS; l++) {
        int flip = l & 1;
        zero_selected<<<12500, 256>>>(0);
        scatter_kernel<<<(MM * 32) / 256, 256>>>(edge_index, flip);
        conv_kernel<<<NN / 8, 128>>>(flip,
                                     sage_Wl + l * HH * HH, sage_bl + l * HH,
                                     sage_Wr + l * HH * HH,
                                     ln_g + l * HH, ln_b + l * HH);
    }

    // global mean
    zero_selected<<<1, 128>>>(2);
    gsum_kernel<<<512, 128>>>();

    // config scoring
    base_kernel<<<NCC, 128>>>(config_ids, cfg_w, cfg_b);
    zero_selected<<<512, 256>>>(3);
    {
        dim3 g(CC / 32, NCC);
        projse_kernel<<<g, 128>>>(config_feat, cfg_w, se_w1, se_b1, se_w2, se_b2);
    }
    {
        dim3 g(HH, 25);
        softmax_kernel<<<g, 512>>>(temperature);
    }
    head_kernel<<<CC, 128>>>(h_w1, h_b1, h_w2, h_b2, h_w3, h_b3, out);
}

// round 3
// speedup vs baseline: 1.1910x; 1.1910x over previous
#include <cuda_runtime.h>
#include <math.h>

#define NN 100000
#define MM 800000
#define HH 128
#define NCC 1000
#define CC 1024
#define NLAYERS 4
#define EPSL 1e-5f

// ---- scratch (static __device__ per harness rules) ----
__device__ float d_h0[NN * HH];
__device__ float d_h1[NN * HH];
__device__ float d_agg[NN * HH];
__device__ float d_invdeg[NN];
__device__ int   d_degi[NN];
__device__ int   d_cursor[NN];
__device__ int   d_rowptr[NN + 1];
__device__ int   d_csr[MM];
__device__ float d_base[NCC * HH];
__device__ float d_P[(size_t)NCC * HH * CC];   // layout [nc][k][c], c contiguous
__device__ float d_cfge[CC * HH];
__device__ float d_gsum[HH];

__device__ __forceinline__ float gelu_f(float x) {
    return 0.5f * x * (1.0f + erff(x * 0.70710678118654752440f));
}

// ---------------- zero helpers ----------------
__global__ void zero_ints() {
    int i = blockIdx.x * 256 + threadIdx.x;
    if (i < NN) { d_degi[i] = 0; d_cursor[i] = 0; }
}
__global__ void zero_floats(int which) {
    size_t n; float* p;
    if (which == 2) { p = d_gsum; n = HH; }
    else { p = d_cfge; n = (size_t)CC * HH; }
    for (size_t i = (size_t)blockIdx.x * blockDim.x + threadIdx.x; i < n;
         i += (size_t)gridDim.x * blockDim.x)
        p[i] = 0.0f;
}

// ---------------- CSR build ----------------
__global__ void degree_kernel(const int* __restrict__ ei) {
    int e = blockIdx.x * 256 + threadIdx.x;
    if (e < MM) atomicAdd(&d_degi[ei[MM + e]], 1);
}

// single block, 1024 threads; each thread handles 98 nodes sequentially
__global__ __launch_bounds__(1024) void scan_kernel() {
    __shared__ int ssum[1024];
    int t = threadIdx.x;
    int start = t * 98;
    int end = start + 98; if (end > NN) end = NN;
    int s = 0;
    for (int i = start; i < end && i < NN; i++) s += d_degi[i];
    ssum[t] = s;
    __syncthreads();
    for (int off = 1; off < 1024; off <<= 1) {
        int add = (t >= off) ? ssum[t - off] : 0;
        __syncthreads();
        ssum[t] += add;
        __syncthreads();
    }
    int run = (t == 0) ? 0 : ssum[t - 1];
    for (int i = start; i < end && i < NN; i++) {
        d_rowptr[i] = run;
        run += d_degi[i];
    }
    if (t == 1023) d_rowptr[NN] = ssum[1023];
}

__global__ void invdeg_kernel() {
    int n = blockIdx.x * 256 + threadIdx.x;
    if (n < NN) d_invdeg[n] = 1.0f / fmaxf((float)d_degi[n], 1.0f);
}

__global__ void csr_fill(const int* __restrict__ ei) {
    int e = blockIdx.x * 256 + threadIdx.x;
    if (e >= MM) return;
    int s = ei[e], d = ei[MM + e];
    int pos = atomicAdd(&d_cursor[d], 1);
    d_csr[d_rowptr[d] + pos] = s;
}

// ---------------- input embed + proj + LN + gelu ----------------
__global__ __launch_bounds__(128) void input_kernel(
    const float* __restrict__ nf, const int* __restrict__ opc,
    const float* __restrict__ depth, const float* __restrict__ emb,
    const float* __restrict__ w, const float* __restrict__ b,
    const float* __restrict__ g, const float* __restrict__ beta)
{
    __shared__ __align__(16) float xs[4 * 208];
    __shared__ float red[8];
    int tid = threadIdx.x;
    int n0 = blockIdx.x * 4;
    for (int i = 0; i < 4; i++) {
        int n = n0 + i;
        for (int d = tid; d < 140; d += 128) xs[i * 208 + d] = nf[n * 140 + d];
        int oc = opc[n]; oc = oc < 0 ? 0 : (oc > 119 ? 119 : oc);
        if (tid < 64) xs[i * 208 + 140 + tid] = emb[oc * 64 + tid];
        if (tid == 0) {
            xs[i * 208 + 204] = depth[n];
            xs[i * 208 + 205] = 0.f; xs[i * 208 + 206] = 0.f; xs[i * 208 + 207] = 0.f;
        }
    }
    __syncthreads();
    int k = tid;
    float acc[4];
    float bb = b[k];
#pragma unroll
    for (int i = 0; i < 4; i++) acc[i] = bb;
    for (int d = 0; d < 204; d += 4) {
        float w0 = w[(d + 0) * 128 + k];
        float w1 = w[(d + 1) * 128 + k];
        float w2 = w[(d + 2) * 128 + k];
        float w3 = w[(d + 3) * 128 + k];
#pragma unroll
        for (int i = 0; i < 4; i++) {
            float4 a = *(const float4*)&xs[i * 208 + d];
            acc[i] += a.x * w0 + a.y * w1 + a.z * w2 + a.w * w3;
        }
    }
    {
        float wv = w[204 * 128 + k];
#pragma unroll
        for (int i = 0; i < 4; i++) acc[i] += xs[i * 208 + 204] * wv;
    }
    float gk = g[k], bk = beta[k];
    for (int i = 0; i < 4; i++) {
        float v = acc[i];
        float s = v, s2 = v * v;
        for (int o = 16; o > 0; o >>= 1) {
            s += __shfl_down_sync(0xffffffffu, s, o);
            s2 += __shfl_down_sync(0xffffffffu, s2, o);
        }
        if ((tid & 31) == 0) { red[tid >> 5] = s; red[4 + (tid >> 5)] = s2; }
        __syncthreads();
        float mu = (red[0] + red[1] + red[2] + red[3]) * (1.0f / 128.0f);
        float ms = (red[4] + red[5] + red[6] + red[7]) * (1.0f / 128.0f);
        float r = rsqrtf(ms - mu * mu + EPSL);
        float ln = (v - mu) * r * gk + bk;
        d_h0[(n0 + i) * 128 + k] = gelu_f(ln);
        __syncthreads();
    }
}

// ---------------- CSR gather (mean aggregation, invdeg fused) --------------
__global__ __launch_bounds__(256) void gather_kernel(int flip) {
    const float* hin = flip ? d_h1 : d_h0;
    int gid = blockIdx.x * 256 + threadIdx.x;
    int n = gid >> 5;
    if (n >= NN) return;
    int lane = gid & 31;
    int beg = d_rowptr[n], end2 = d_rowptr[n + 1];
    float4 v = make_float4(0.f, 0.f, 0.f, 0.f);
    for (int j = beg; j < end2; j++) {
        int s = d_csr[j];
        float4 x = ((const float4*)(hin + (size_t)s * 128))[lane];
        v.x += x.x; v.y += x.y; v.z += x.z; v.w += x.w;
    }
    float id = d_invdeg[n];
    ((float4*)(d_agg + (size_t)n * 128))[lane] =
        make_float4(v.x * id, v.y * id, v.z * id, v.w * id);
}

// ---------------- SAGE conv as register-tiled SGEMM + residual + LN --------
// C[128 nodes x 128 cols] = [agg | h] (128x256) @ [Wl;Wr] (256x128)
// block 256 threads, 8x8 accumulators per thread
__global__ __launch_bounds__(256) void conv_kernel(
    int flip, const float* __restrict__ Wl, const float* __restrict__ bl,
    const float* __restrict__ Wr, const float* __restrict__ lg,
    const float* __restrict__ lb)
{
    const float* hin = flip ? d_h1 : d_h0;
    float* hout = flip ? d_h0 : d_h1;
    __shared__ float As[16][129];
    __shared__ float Bs[16][128];
    __shared__ float redS[128][17];
    __shared__ float redQ[128][17];

    int tid = threadIdx.x;
    int m0 = blockIdx.x * 128;
    int tr = tid >> 4;          // 0..15 row group
    int tc = tid & 15;          // 0..15 col group
    int r0 = tr * 8, c0 = tc * 8;
    float acc[8][8];
#pragma unroll
    for (int i = 0; i < 8; i++)
#pragma unroll
        for (int j = 0; j < 8; j++) acc[i][j] = 0.0f;

    int am = tid >> 1, ak = (tid & 1) * 8;     // A load: row am, k ak..ak+7
    int bn = (tid & 31) * 4, bk = tid >> 5;    // B load: k = bk, bk+8

    for (int k0 = 0; k0 < 256; k0 += 16) {
        int gm = m0 + am;
#pragma unroll
        for (int kk = 0; kk < 8; kk++) {
            int k = ak + kk;
            int gk = k0 + k;
            float v = 0.0f;
            if (gm < NN)
                v = (gk < 128) ? d_agg[(size_t)gm * 128 + gk]
                               : hin[(size_t)gm * 128 + (gk - 128)];
            As[k][am] = v;
        }
#pragma unroll
        for (int kk = 0; kk < 2; kk++) {
            int k = bk + kk * 8;
            int gk = k0 + k;
            const float* src = (gk < 128) ? (Wl + (size_t)gk * 128)
                                          : (Wr + (size_t)(gk - 128) * 128);
            *(float4*)&Bs[k][bn] = *(const float4*)(src + bn);
        }
        __syncthreads();
#pragma unroll
        for (int k = 0; k < 16; k++) {
            float a[8], b[8];
#pragma unroll
            for (int i = 0; i < 8; i++) a[i] = As[k][r0 + i];
            float4 b0 = *(const float4*)&Bs[k][c0];
            float4 b1 = *(const float4*)&Bs[k][c0 + 4];
            b[0] = b0.x; b[1] = b0.y; b[2] = b0.z; b[3] = b0.w;
            b[4] = b1.x; b[5] = b1.y; b[6] = b1.z; b[7] = b1.w;
#pragma unroll
            for (int i = 0; i < 8; i++)
#pragma unroll
                for (int j = 0; j < 8; j++) acc[i][j] += a[i] * b[j];
        }
        __syncthreads();
    }

    float bias[8], gv8[8], bv8[8];
#pragma unroll
    for (int j = 0; j < 8; j++) {
        bias[j] = bl[c0 + j];
        gv8[j] = lg[c0 + j];
        bv8[j] = lb[c0 + j];
    }
#pragma unroll
    for (int i = 0; i < 8; i++) {
        int gm = m0 + r0 + i;
        float psum = 0.0f, psq = 0.0f;
        if (gm < NN) {
#pragma unroll
            for (int j = 0; j < 8; j++) {
                float res = hin[(size_t)gm * 128 + c0 + j];
                float gvv = res + gelu_f(acc[i][j] + bias[j]);
                acc[i][j] = gvv;
                psum += gvv; psq += gvv * gvv;
            }
        }
        redS[r0 + i][tc] = psum;
        redQ[r0 + i][tc] = psq;
    }
    __syncthreads();
#pragma unroll
    for (int i = 0; i < 8; i++) {
        int gm = m0 + r0 + i;
        if (gm >= NN) continue;
        float s = 0.0f, q = 0.0f;
#pragma unroll
        for (int p = 0; p < 16; p++) { s += redS[r0 + i][p]; q += redQ[r0 + i][p]; }
        float mu = s * (1.0f / 128.0f);
        float var = q * (1.0f / 128.0f) - mu * mu;
        float rr = rsqrtf(var + EPSL);
#pragma unroll
        for (int j = 0; j < 8; j++)
            hout[(size_t)gm * 128 + c0 + j] = (acc[i][j] - mu) * rr * gv8[j] + bv8[j];
    }
}

// ---------------- global mean partials (final h lives in d_h0) -------------
__global__ __launch_bounds__(128) void gsum_kernel() {
    int k = threadIdx.x;
    float s = 0.0f;
    for (int n = blockIdx.x; n < NN; n += gridDim.x) s += d_h0[(size_t)n * 128 + k];
    atomicAdd(&d_gsum[k], s);
}

// ---------------- base[nc] = h[config_ids[nc]] @ cfg_w[:128] + cfg_b -------
__global__ __launch_bounds__(128) void base_kernel(
    const int* __restrict__ cid, const float* __restrict__ cw,
    const float* __restrict__ cb)
{
    __shared__ float hs[128];
    int nc = blockIdx.x, k = threadIdx.x;
    int node = cid[nc];
    hs[k] = d_h0[(size_t)node * 128 + k];
    __syncthreads();
    float a = cb[k];
    for (int d = 0; d < 128; d++) a += hs[d] * cw[d * 128 + k];
    d_base[nc * 128 + k] = a;
}

// ---------------- proj (18-wide) + SE, store transposed into d_P -----------
__global__ __launch_bounds__(128) void projse_kernel(
    const float* __restrict__ cf, const float* __restrict__ cw,
    const float* __restrict__ w1, const float* __restrict__ b1,
    const float* __restrict__ w2, const float* __restrict__ b2)
{
    __shared__ float bs[128];
    __shared__ float cws[18 * 128];
    __shared__ float w1s[128 * 16];
    __shared__ float w2s[16 * 128];
    __shared__ float b1s[16], b2s[128];
    __shared__ float vsh[18];
    __shared__ float psh[128];
    __shared__ float rpart[16 * 8];
    __shared__ float rsh[16];
    __shared__ float tile[128 * 33];
    int tid = threadIdx.x;
    int nc = blockIdx.y;
    int c0 = blockIdx.x * 32;
    bs[tid] = d_base[nc * 128 + tid];
    b2s[tid] = b2[tid];
    if (tid < 16) b1s[tid] = b1[tid];
    for (int i = tid; i < 18 * 128; i += 128) cws[i] = cw[128 * 128 + i];
    for (int i = tid; i < 128 * 16; i += 128) w1s[i] = w1[i];
    for (int i = tid; i < 16 * 128; i += 128) w2s[i] = w2[i];
    __syncthreads();
    int k = tid;
    for (int ci = 0; ci < 32; ci++) {
        int c = c0 + ci;
        if (tid < 18) vsh[tid] = cf[((size_t)c * NCC + nc) * 18 + tid];
        __syncthreads();
        float t = bs[k];
#pragma unroll
        for (int d = 0; d < 18; d++) t += vsh[d] * cws[d * 128 + k];
        float p = gelu_f(t);
        psh[k] = p;
        __syncthreads();
        {
            int j = tid & 15, gg = tid >> 4;
            float part = 0.0f;
#pragma unroll
            for (int q = 0; q < 16; q++) {
                int kk = gg * 16 + q;
                part += psh[kk] * w1s[kk * 16 + j];
            }
            rpart[j * 8 + gg] = part;
        }
        __syncthreads();
        if (tid < 16) {
            float r = b1s[tid];
#pragma unroll
            for (int gg = 0; gg < 8; gg++) r += rpart[tid * 8 + gg];
            rsh[tid] = fmaxf(r, 0.0f);
        }
        __syncthreads();
        float sv = b2s[k];
#pragma unroll
        for (int j = 0; j < 16; j++) sv += rsh[j] * w2s[j * 128 + k];
        float sig = 1.0f / (1.0f + expf(-sv));
        tile[k * 33 + ci] = p * sig;
        __syncthreads();
    }
    for (int idx = tid; idx < 128 * 32; idx += 128) {
        int kk = idx >> 5, j = idx & 31;
        d_P[(size_t)nc * (HH * CC) + (size_t)kk * CC + c0 + j] = tile[kk * 33 + j];
    }
}

// ---------------- chunked softmax over configs + mean over nc --------------
__global__ __launch_bounds__(512) void softmax_kernel(const float* __restrict__ temp) {
    __shared__ float sbuf[16];
    int tid = threadIdx.x;
    int k = blockIdx.x;
    int grp = blockIdx.y;
    float invT = 1.0f / temp[0];
    float acc0 = 0.0f, acc1 = 0.0f;
    for (int nc = grp * 40; nc < grp * 40 + 40; nc++) {
        size_t rb = (size_t)nc * (HH * CC) + (size_t)k * CC;
#pragma unroll
        for (int c2 = 0; c2 < 2; c2++) {
            float x = d_P[rb + c2 * 512 + tid];
            float y = x * invT;
            float m = y;
            for (int o = 16; o > 0; o >>= 1) m = fmaxf(m, __shfl_xor_sync(0xffffffffu, m, o));
            if ((tid & 31) == 0) sbuf[tid >> 5] = m;
            __syncthreads();
            m = sbuf[0];
#pragma unroll
            for (int w = 1; w < 16; w++) m = fmaxf(m, sbuf[w]);
            __syncthreads();
            float e = expf(y - m);
            float s = e;
            for (int o = 16; o > 0; o >>= 1) s += __shfl_xor_sync(0xffffffffu, s, o);
            if ((tid & 31) == 0) sbuf[tid >> 5] = s;
            __syncthreads();
            s = 0.0f;
#pragma unroll
            for (int w = 0; w < 16; w++) s += sbuf[w];
            __syncthreads();
            float contrib = x * (e / s);
            if (c2 == 0) acc0 += contrib; else acc1 += contrib;
        }
    }
    atomicAdd(&d_cfge[(0 * 512 + tid) * 128 + k], acc0 * (1.0f / (float)NCC));
    atomicAdd(&d_cfge[(512 + tid) * 128 + k], acc1 * (1.0f / (float)NCC));
}

// ---------------- scoring head ----------------
__global__ __launch_bounds__(128) void head_kernel(
    const float* __restrict__ w1, const float* __restrict__ b1v,
    const float* __restrict__ w2, const float* __restrict__ b2v,
    const float* __restrict__ w3, const float* __restrict__ b3v,
    float* __restrict__ out)
{
    __shared__ float fin[256];
    __shared__ float x1[128];
    __shared__ float x2[64];
    int tid = threadIdx.x;
    int c = blockIdx.x;
    fin[tid] = d_gsum[tid] * (1.0f / (float)NN);
    fin[128 + tid] = d_cfge[c * 128 + tid];
    __syncthreads();
    float a = b1v[tid];
    for (int d = 0; d < 256; d++) a += fin[d] * w1[d * 128 + tid];
    x1[tid] = gelu_f(a);
    __syncthreads();
    if (tid < 64) {
        float a2 = b2v[tid];
        for (int d = 0; d < 128; d++) a2 += x1[d] * w2[d * 64 + tid];
        x2[tid] = gelu_f(a2);
    }
    __syncthreads();
    if (tid == 0) {
        float s = b3v[0];
        for (int d = 0; d < 64; d++) s += x2[d] * w3[d];
        out[c] = s;
    }
}

extern "C" void kernel_launch(void* const* d_in, const int* in_sizes, int n_in,
                              void* d_out, int out_size) {
    const float* node_feat     = (const float*)d_in[0];
    const int*   node_opcode   = (const int*)  d_in[1];
    const float* topo_depth    = (const float*)d_in[2];
    const int*   edge_index    = (const int*)  d_in[3];
    const int*   config_ids    = (const int*)  d_in[4];
    const float* config_feat   = (const float*)d_in[5];
    const float* temperature   = (const float*)d_in[6];
    const float* opcode_embed  = (const float*)d_in[7];
    const float* in_w          = (const float*)d_in[8];
    const float* in_b          = (const float*)d_in[9];
    const float* in_g          = (const float*)d_in[10];
    const float* in_beta       = (const float*)d_in[11];
    const float* sage_Wl       = (const float*)d_in[12];
    const float* sage_bl       = (const float*)d_in[13];
    const float* sage_Wr       = (const float*)d_in[14];
    const float* ln_g          = (const float*)d_in[15];
    const float* ln_b          = (const float*)d_in[16];
    const float* cfg_w         = (const float*)d_in[17];
    const float* cfg_b         = (const float*)d_in[18];
    const float* se_w1         = (const float*)d_in[19];
    const float* se_b1         = (const float*)d_in[20];
    const float* se_w2         = (const float*)d_in[21];
    const float* se_b2         = (const float*)d_in[22];
    const float* h_w1          = (const float*)d_in[23];
    const float* h_b1          = (const float*)d_in[24];
    const float* h_w2          = (const float*)d_in[25];
    const float* h_b2          = (const float*)d_in[26];
    const float* h_w3          = (const float*)d_in[27];
    const float* h_b3          = (const float*)d_in[28];
    float* out = (float*)d_out;

    // CSR build
    zero_ints<<<(NN + 255) / 256, 256>>>();
    degree_kernel<<<(MM + 255) / 256, 256>>>(edge_index);
    scan_kernel<<<1, 1024>>>();
    invdeg_kernel<<<(NN + 255) / 256, 256>>>();
    csr_fill<<<(MM + 255) / 256, 256>>>(edge_index);

    // input embedding + projection
    input_kernel<<<NN / 4, 128>>>(node_feat, node_opcode, topo_depth, opcode_embed,
                                  in_w, in_b, in_g, in_beta);

    // 4 SAGE layers
    for (int l = 0; l < NLAYERS; l++) {
        int flip = l & 1;
        gather_kernel<<<(NN * 32 + 255) / 256, 256>>>(flip);
        conv_kernel<<<(NN + 127) / 128, 256>>>(flip,
                                     sage_Wl + l * HH * HH, sage_bl + l * HH,
                                     sage_Wr + l * HH * HH,
                                     ln_g + l * HH, ln_b + l * HH);
    }

    // global mean
    zero_floats<<<1, 128>>>(2);
    gsum_kernel<<<512, 128>>>();

    // config scoring
    base_kernel<<<NCC, 128>>>(config_ids, cfg_w, cfg_b);
    zero_floats<<<512, 256>>>(3);
    {
        dim3 g(CC / 32, NCC);
        projse_kernel<<<g, 128>>>(config_feat, cfg_w, se_w1, se_b1, se_w2, se_b2);
    }
    {
        dim3 g(HH, 25);
        softmax_kernel<<<g, 512>>>(temperature);
    }
    head_kernel<<<CC, 128>>>(h_w1, h_b1, h_w2, h_b2, h_w3, h_b3, out);
}

// round 5
// speedup vs baseline: 1.2321x; 1.0346x over previous
#include <cuda_runtime.h>
#include <math.h>
#include <stdint.h>

#define NN 100000
#define MM 800000
#define HH 128
#define NCC 1000
#define CC 1024
#define NLAYERS 4
#define EPSL 1e-5f

// ---- scratch (static __device__ per harness rules) ----
__device__ float d_h0[NN * HH];
__device__ float d_h1[NN * HH];
__device__ float d_agg[NN * HH];
__device__ float d_invdeg[NN];
__device__ int   d_degi[NN];
__device__ int   d_cursor[NN];
__device__ int   d_rowptr[NN + 1];
__device__ int   d_csr[MM];
__device__ float d_base[NCC * HH];
__device__ float d_P[(size_t)NCC * HH * CC];   // layout [nc][k][c], c contiguous
__device__ float d_cfge[CC * HH];
__device__ float d_gsum[HH];

__device__ __forceinline__ float gelu_f(float x) {
    return 0.5f * x * (1.0f + erff(x * 0.70710678118654752440f));
}

__device__ __forceinline__ void split_tf32(float x, float& hi, float& lo) {
    uint32_t h;
    asm("cvt.rna.tf32.f32 %0, %1;" : "=r"(h) : "f"(x));
    float hf = __uint_as_float(h);
    float r = x - hf;
    uint32_t l;
    asm("cvt.rna.tf32.f32 %0, %1;" : "=r"(l) : "f"(r));
    hi = hf;
    lo = __uint_as_float(l);
}

__device__ __forceinline__ void mma_tf32(float* c, const uint32_t* a, const uint32_t* b) {
    asm volatile(
        "mma.sync.aligned.m16n8k8.row.col.f32.tf32.tf32.f32 "
        "{%0,%1,%2,%3}, {%4,%5,%6,%7}, {%8,%9}, {%0,%1,%2,%3};"
        : "+f"(c[0]), "+f"(c[1]), "+f"(c[2]), "+f"(c[3])
        : "r"(a[0]), "r"(a[1]), "r"(a[2]), "r"(a[3]), "r"(b[0]), "r"(b[1]));
}

// ---------------- zero helpers ----------------
__global__ void zero_ints() {
    int i = blockIdx.x * 256 + threadIdx.x;
    if (i < NN) { d_degi[i] = 0; d_cursor[i] = 0; }
}
__global__ void zero_floats(int which) {
    size_t n; float* p;
    if (which == 2) { p = d_gsum; n = HH; }
    else { p = d_cfge; n = (size_t)CC * HH; }
    for (size_t i = (size_t)blockIdx.x * blockDim.x + threadIdx.x; i < n;
         i += (size_t)gridDim.x * blockDim.x)
        p[i] = 0.0f;
}

// ---------------- CSR build ----------------
__global__ void degree_kernel(const int* __restrict__ ei) {
    int e = blockIdx.x * 256 + threadIdx.x;
    if (e < MM) atomicAdd(&d_degi[ei[MM + e]], 1);
}

__global__ __launch_bounds__(1024) void scan_kernel() {
    __shared__ int ssum[1024];
    int t = threadIdx.x;
    int start = t * 98;
    int end = start + 98; if (end > NN) end = NN;
    int s = 0;
    for (int i = start; i < end && i < NN; i++) s += d_degi[i];
    ssum[t] = s;
    __syncthreads();
    for (int off = 1; off < 1024; off <<= 1) {
        int add = (t >= off) ? ssum[t - off] : 0;
        __syncthreads();
        ssum[t] += add;
        __syncthreads();
    }
    int run = (t == 0) ? 0 : ssum[t - 1];
    for (int i = start; i < end && i < NN; i++) {
        d_rowptr[i] = run;
        run += d_degi[i];
    }
    if (t == 1023) d_rowptr[NN] = ssum[1023];
}

__global__ void invdeg_kernel() {
    int n = blockIdx.x * 256 + threadIdx.x;
    if (n < NN) d_invdeg[n] = 1.0f / fmaxf((float)d_degi[n], 1.0f);
}

__global__ void csr_fill(const int* __restrict__ ei) {
    int e = blockIdx.x * 256 + threadIdx.x;
    if (e >= MM) return;
    int s = ei[e], d = ei[MM + e];
    int pos = atomicAdd(&d_cursor[d], 1);
    d_csr[d_rowptr[d] + pos] = s;
}

// ---------------- input embed + proj + LN + gelu ----------------
__global__ __launch_bounds__(128) void input_kernel(
    const float* __restrict__ nf, const int* __restrict__ opc,
    const float* __restrict__ depth, const float* __restrict__ emb,
    const float* __restrict__ w, const float* __restrict__ b,
    const float* __restrict__ g, const float* __restrict__ beta)
{
    __shared__ __align__(16) float xs[4 * 208];
    __shared__ float red[8];
    int tid = threadIdx.x;
    int n0 = blockIdx.x * 4;
    for (int i = 0; i < 4; i++) {
        int n = n0 + i;
        for (int d = tid; d < 140; d += 128) xs[i * 208 + d] = nf[n * 140 + d];
        int oc = opc[n]; oc = oc < 0 ? 0 : (oc > 119 ? 119 : oc);
        if (tid < 64) xs[i * 208 + 140 + tid] = emb[oc * 64 + tid];
        if (tid == 0) {
            xs[i * 208 + 204] = depth[n];
            xs[i * 208 + 205] = 0.f; xs[i * 208 + 206] = 0.f; xs[i * 208 + 207] = 0.f;
        }
    }
    __syncthreads();
    int k = tid;
    float acc[4];
    float bb = b[k];
#pragma unroll
    for (int i = 0; i < 4; i++) acc[i] = bb;
    for (int d = 0; d < 204; d += 4) {
        float w0 = w[(d + 0) * 128 + k];
        float w1 = w[(d + 1) * 128 + k];
        float w2 = w[(d + 2) * 128 + k];
        float w3 = w[(d + 3) * 128 + k];
#pragma unroll
        for (int i = 0; i < 4; i++) {
            float4 a = *(const float4*)&xs[i * 208 + d];
            acc[i] += a.x * w0 + a.y * w1 + a.z * w2 + a.w * w3;
        }
    }
    {
        float wv = w[204 * 128 + k];
#pragma unroll
        for (int i = 0; i < 4; i++) acc[i] += xs[i * 208 + 204] * wv;
    }
    float gk = g[k], bk = beta[k];
    for (int i = 0; i < 4; i++) {
        float v = acc[i];
        float s = v, s2 = v * v;
        for (int o = 16; o > 0; o >>= 1) {
            s += __shfl_down_sync(0xffffffffu, s, o);
            s2 += __shfl_down_sync(0xffffffffu, s2, o);
        }
        if ((tid & 31) == 0) { red[tid >> 5] = s; red[4 + (tid >> 5)] = s2; }
        __syncthreads();
        float mu = (red[0] + red[1] + red[2] + red[3]) * (1.0f / 128.0f);
        float ms = (red[4] + red[5] + red[6] + red[7]) * (1.0f / 128.0f);
        float r = rsqrtf(ms - mu * mu + EPSL);
        float ln = (v - mu) * r * gk + bk;
        d_h0[(n0 + i) * 128 + k] = gelu_f(ln);
        __syncthreads();
    }
}

// ---------------- CSR gather (mean aggregation, invdeg fused) --------------
__global__ __launch_bounds__(256) void gather_kernel(int flip) {
    const float* hin = flip ? d_h1 : d_h0;
    int gid = blockIdx.x * 256 + threadIdx.x;
    int n = gid >> 5;
    if (n >= NN) return;
    int lane = gid & 31;
    int beg = d_rowptr[n], end2 = d_rowptr[n + 1];
    float4 v = make_float4(0.f, 0.f, 0.f, 0.f);
    for (int j = beg; j < end2; j++) {
        int s = d_csr[j];
        float4 x = ((const float4*)(hin + (size_t)s * 128))[lane];
        v.x += x.x; v.y += x.y; v.z += x.z; v.w += x.w;
    }
    float id = d_invdeg[n];
    ((float4*)(d_agg + (size_t)n * 128))[lane] =
        make_float4(v.x * id, v.y * id, v.z * id, v.w * id);
}

// ---------------- SAGE conv via tf32 split mma + residual + LN ------------
// C[128 x 128] = [agg | h](128x256) @ [Wl;Wr](256x128); 256 thr, 8 warps 32x64
__global__ __launch_bounds__(256) void conv_kernel(
    int flip, const float* __restrict__ Wl, const float* __restrict__ bl,
    const float* __restrict__ Wr, const float* __restrict__ lg,
    const float* __restrict__ lb)
{
    const float* hin = flip ? d_h1 : d_h0;
    float* hout = flip ? d_h0 : d_h1;
    __shared__ float Ah[16][136], Al[16][136];
    __shared__ float Bh[16][132], Bl[16][132];
    __shared__ float redS[128][2], redQ[128][2];
    __shared__ float biasS[128], gS[128], bS[128];

    int tid = threadIdx.x;
    int m0 = blockIdx.x * 128;
    int lane = tid & 31, w = tid >> 5;
    int g = lane >> 2, t4 = lane & 3;
    int wr = w & 3, wc = w >> 2;
    int mwarp = wr * 32, nbase = wc * 64;

    if (tid < 128) { biasS[tid] = bl[tid]; gS[tid] = lg[tid]; bS[tid] = lb[tid]; }

    float c[2][8][4];
#pragma unroll
    for (int mt = 0; mt < 2; mt++)
#pragma unroll
        for (int nt = 0; nt < 8; nt++)
#pragma unroll
            for (int q = 0; q < 4; q++) c[mt][nt][q] = 0.0f;

    int am = tid >> 1, aseg = (tid & 1) * 8;     // A: row am, local k aseg..+7
    int bkr = tid >> 4, bn0 = (tid & 15) * 8;    // B: k-row bkr, cols bn0..+7

    for (int k0 = 0; k0 < 256; k0 += 16) {
        // ---- stage A chunk (128 x 16) ----
        const float* Asrc = (k0 < 128) ? d_agg : hin;
        int kb = (k0 < 128) ? k0 : (k0 - 128);
        int gm = m0 + am;
        float av[8];
        if (gm < NN) {
            const float4* p = (const float4*)(Asrc + (size_t)gm * 128 + kb + aseg);
            float4 v0 = p[0], v1 = p[1];
            av[0] = v0.x; av[1] = v0.y; av[2] = v0.z; av[3] = v0.w;
            av[4] = v1.x; av[5] = v1.y; av[6] = v1.z; av[7] = v1.w;
        } else {
#pragma unroll
            for (int i = 0; i < 8; i++) av[i] = 0.0f;
        }
#pragma unroll
        for (int i = 0; i < 8; i++) {
            float hi, lo; split_tf32(av[i], hi, lo);
            Ah[aseg + i][am] = hi; Al[aseg + i][am] = lo;
        }
        // ---- stage B chunk (16 x 128) ----
        const float* Bsrc = (k0 < 128) ? Wl : Wr;
        const float4* q4 = (const float4*)(Bsrc + (size_t)(kb + bkr) * 128 + bn0);
        float4 u0 = q4[0], u1 = q4[1];
        float bv[8] = {u0.x, u0.y, u0.z, u0.w, u1.x, u1.y, u1.z, u1.w};
#pragma unroll
        for (int i = 0; i < 8; i++) {
            float hi, lo; split_tf32(bv[i], hi, lo);
            Bh[bkr][bn0 + i] = hi; Bl[bkr][bn0 + i] = lo;
        }
        __syncthreads();
        // ---- mma over 2 k-tiles of 8 ----
#pragma unroll
        for (int kt = 0; kt < 16; kt += 8) {
            uint32_t ah[2][4], al[2][4];
#pragma unroll
            for (int mt = 0; mt < 2; mt++) {
                int mo = mwarp + mt * 16;
                ah[mt][0] = __float_as_uint(Ah[kt + t4][mo + g]);
                ah[mt][1] = __float_as_uint(Ah[kt + t4][mo + g + 8]);
                ah[mt][2] = __float_as_uint(Ah[kt + t4 + 4][mo + g]);
                ah[mt][3] = __float_as_uint(Ah[kt + t4 + 4][mo + g + 8]);
                al[mt][0] = __float_as_uint(Al[kt + t4][mo + g]);
                al[mt][1] = __float_as_uint(Al[kt + t4][mo + g + 8]);
                al[mt][2] = __float_as_uint(Al[kt + t4 + 4][mo + g]);
                al[mt][3] = __float_as_uint(Al[kt + t4 + 4][mo + g + 8]);
            }
            uint32_t bh[8][2], blo[8][2];
#pragma unroll
            for (int nt = 0; nt < 8; nt++) {
                int col = nbase + nt * 8 + g;
                bh[nt][0]  = __float_as_uint(Bh[kt + t4][col]);
                bh[nt][1]  = __float_as_uint(Bh[kt + t4 + 4][col]);
                blo[nt][0] = __float_as_uint(Bl[kt + t4][col]);
                blo[nt][1] = __float_as_uint(Bl[kt + t4 + 4][col]);
            }
#pragma unroll
            for (int mt = 0; mt < 2; mt++)
#pragma unroll
                for (int nt = 0; nt < 8; nt++) {
                    mma_tf32(c[mt][nt], ah[mt], bh[nt]);
                    mma_tf32(c[mt][nt], ah[mt], blo[nt]);
                    mma_tf32(c[mt][nt], al[mt], bh[nt]);
                }
        }
        __syncthreads();
    }

    // ---- epilogue: residual + gelu + LN ----
#pragma unroll
    for (int mt = 0; mt < 2; mt++) {
        int lrA = mwarp + mt * 16 + g;
        int lrB = lrA + 8;
        int gA = m0 + lrA, gB = m0 + lrB;
        float sA = 0, qA = 0, sB = 0, qB = 0;
#pragma unroll
        for (int nt = 0; nt < 8; nt++) {
            int col = nbase + nt * 8 + 2 * t4;
            float rA0 = 0, rA1 = 0, rB0 = 0, rB1 = 0;
            if (gA < NN) {
                float2 r2 = *(const float2*)(hin + (size_t)gA * 128 + col);
                rA0 = r2.x; rA1 = r2.y;
            }
            if (gB < NN) {
                float2 r2 = *(const float2*)(hin + (size_t)gB * 128 + col);
                rB0 = r2.x; rB1 = r2.y;
            }
            float v;
            v = rA0 + gelu_f(c[mt][nt][0] + biasS[col]);     c[mt][nt][0] = v; sA += v; qA += v * v;
            v = rA1 + gelu_f(c[mt][nt][1] + biasS[col + 1]); c[mt][nt][1] = v; sA += v; qA += v * v;
            v = rB0 + gelu_f(c[mt][nt][2] + biasS[col]);     c[mt][nt][2] = v; sB += v; qB += v * v;
            v = rB1 + gelu_f(c[mt][nt][3] + biasS[col + 1]); c[mt][nt][3] = v; sB += v; qB += v * v;
        }
        sA += __shfl_xor_sync(0xffffffffu, sA, 1); sA += __shfl_xor_sync(0xffffffffu, sA, 2);
        qA += __shfl_xor_sync(0xffffffffu, qA, 1); qA += __shfl_xor_sync(0xffffffffu, qA, 2);
        sB += __shfl_xor_sync(0xffffffffu, sB, 1); sB += __shfl_xor_sync(0xffffffffu, sB, 2);
        qB += __shfl_xor_sync(0xffffffffu, qB, 1); qB += __shfl_xor_sync(0xffffffffu, qB, 2);
        if (t4 == 0) {
            redS[lrA][wc] = sA; redQ[lrA][wc] = qA;
            redS[lrB][wc] = sB; redQ[lrB][wc] = qB;
        }
    }
    __syncthreads();
#pragma unroll
    for (int mt = 0; mt < 2; mt++) {
        int lrA = mwarp + mt * 16 + g;
        int lrB = lrA + 8;
        int gA = m0 + lrA, gB = m0 + lrB;
        float muA = (redS[lrA][0] + redS[lrA][1]) * (1.0f / 128.0f);
        float vaA = (redQ[lrA][0] + redQ[lrA][1]) * (1.0f / 128.0f) - muA * muA;
        float rrA = rsqrtf(vaA + EPSL);
        float muB = (redS[lrB][0] + redS[lrB][1]) * (1.0f / 128.0f);
        float vaB = (redQ[lrB][0] + redQ[lrB][1]) * (1.0f / 128.0f) - muB * muB;
        float rrB = rsqrtf(vaB + EPSL);
#pragma unroll
        for (int nt = 0; nt < 8; nt++) {
            int col = nbase + nt * 8 + 2 * t4;
            if (gA < NN) {
                float2 o;
                o.x = (c[mt][nt][0] - muA) * rrA * gS[col] + bS[col];
                o.y = (c[mt][nt][1] - muA) * rrA * gS[col + 1] + bS[col + 1];
                *(float2*)(hout + (size_t)gA * 128 + col) = o;
            }
            if (gB < NN) {
                float2 o;
                o.x = (c[mt][nt][2] - muB) * rrB * gS[col] + bS[col];
                o.y = (c[mt][nt][3] - muB) * rrB * gS[col + 1] + bS[col + 1];
                *(float2*)(hout + (size_t)gB * 128 + col) = o;
            }
        }
    }
}

// ---------------- global mean partials (final h lives in d_h0) -------------
__global__ __launch_bounds__(128) void gsum_kernel() {
    int k = threadIdx.x;
    float s = 0.0f;
    for (int n = blockIdx.x; n < NN; n += gridDim.x) s += d_h0[(size_t)n * 128 + k];
    atomicAdd(&d_gsum[k], s);
}

// ---------------- base[nc] = h[config_ids[nc]] @ cfg_w[:128] + cfg_b -------
__global__ __launch_bounds__(128) void base_kernel(
    const int* __restrict__ cid, const float* __restrict__ cw,
    const float* __restrict__ cb)
{
    __shared__ float hs[128];
    int nc = blockIdx.x, k = threadIdx.x;
    int node = cid[nc];
    hs[k] = d_h0[(size_t)node * 128 + k];
    __syncthreads();
    float a = cb[k];
    for (int d = 0; d < 128; d++) a += hs[d] * cw[d * 128 + k];
    d_base[nc * 128 + k] = a;
}

// ---------------- proj (18-wide) + SE, store transposed into d_P -----------
__global__ __launch_bounds__(128) void projse_kernel(
    const float* __restrict__ cf, const float* __restrict__ cw,
    const float* __restrict__ w1, const float* __restrict__ b1,
    const float* __restrict__ w2, const float* __restrict__ b2)
{
    __shared__ float bs[128];
    __shared__ float cws[18 * 128];
    __shared__ float w1s[128 * 16];
    __shared__ float w2s[16 * 128];
    __shared__ float b1s[16], b2s[128];
    __shared__ float vsh[18];
    __shared__ float psh[128];
    __shared__ float rpart[16 * 8];
    __shared__ float rsh[16];
    __shared__ float tile[128 * 33];
    int tid = threadIdx.x;
    int nc = blockIdx.y;
    int c0 = blockIdx.x * 32;
    bs[tid] = d_base[nc * 128 + tid];
    b2s[tid] = b2[tid];
    if (tid < 16) b1s[tid] = b1[tid];
    for (int i = tid; i < 18 * 128; i += 128) cws[i] = cw[128 * 128 + i];
    for (int i = tid; i < 128 * 16; i += 128) w1s[i] = w1[i];
    for (int i = tid; i < 16 * 128; i += 128) w2s[i] = w2[i];
    __syncthreads();
    int k = tid;
    for (int ci = 0; ci < 32; ci++) {
        int c = c0 + ci;
        if (tid < 18) vsh[tid] = cf[((size_t)c * NCC + nc) * 18 + tid];
        __syncthreads();
        float t = bs[k];
#pragma unroll
        for (int d = 0; d < 18; d++) t += vsh[d] * cws[d * 128 + k];
        float p = gelu_f(t);
        psh[k] = p;
        __syncthreads();
        {
            int j = tid & 15, gg = tid >> 4;
            float part = 0.0f;
#pragma unroll
            for (int q = 0; q < 16; q++) {
                int kk = gg * 16 + q;
                part += psh[kk] * w1s[kk * 16 + j];
            }
            rpart[j * 8 + gg] = part;
        }
        __syncthreads();
        if (tid < 16) {
            float r = b1s[tid];
#pragma unroll
            for (int gg = 0; gg < 8; gg++) r += rpart[tid * 8 + gg];
            rsh[tid] = fmaxf(r, 0.0f);
        }
        __syncthreads();
        float sv = b2s[k];
#pragma unroll
        for (int j = 0; j < 16; j++) sv += rsh[j] * w2s[j * 128 + k];
        float sig = 1.0f / (1.0f + expf(-sv));
        tile[k * 33 + ci] = p * sig;
        __syncthreads();
    }
    for (int idx = tid; idx < 128 * 32; idx += 128) {
        int kk = idx >> 5, j = idx & 31;
        d_P[(size_t)nc * (HH * CC) + (size_t)kk * CC + c0 + j] = tile[kk * 33 + j];
    }
}

// ---------------- chunked softmax over configs + mean over nc --------------
__global__ __launch_bounds__(512) void softmax_kernel(const float* __restrict__ temp) {
    __shared__ float sbuf[16];
    int tid = threadIdx.x;
    int k = blockIdx.x;
    int grp = blockIdx.y;
    float invT = 1.0f / temp[0];
    float acc0 = 0.0f, acc1 = 0.0f;
    for (int nc = grp * 40; nc < grp * 40 + 40; nc++) {
        size_t rb = (size_t)nc * (HH * CC) + (size_t)k * CC;
#pragma unroll
        for (int c2 = 0; c2 < 2; c2++) {
            float x = d_P[rb + c2 * 512 + tid];
            float y = x * invT;
            float m = y;
            for (int o = 16; o > 0; o >>= 1) m = fmaxf(m, __shfl_xor_sync(0xffffffffu, m, o));
            if ((tid & 31) == 0) sbuf[tid >> 5] = m;
            __syncthreads();
            m = sbuf[0];
#pragma unroll
            for (int w = 1; w < 16; w++) m = fmaxf(m, sbuf[w]);
            __syncthreads();
            float e = expf(y - m);
            float s = e;
            for (int o = 16; o > 0; o >>= 1) s += __shfl_xor_sync(0xffffffffu, s, o);
            if ((tid & 31) == 0) sbuf[tid >> 5] = s;
            __syncthreads();
            s = 0.0f;
#pragma unroll
            for (int w = 0; w < 16; w++) s += sbuf[w];
            __syncthreads();
            float contrib = x * (e / s);
            if (c2 == 0) acc0 += contrib; else acc1 += contrib;
        }
    }
    atomicAdd(&d_cfge[(0 * 512 + tid) * 128 + k], acc0 * (1.0f / (float)NCC));
    atomicAdd(&d_cfge[(512 + tid) * 128 + k], acc1 * (1.0f / (float)NCC));
}

// ---------------- scoring head ----------------
__global__ __launch_bounds__(128) void head_kernel(
    const float* __restrict__ w1, const float* __restrict__ b1v,
    const float* __restrict__ w2, const float* __restrict__ b2v,
    const float* __restrict__ w3, const float* __restrict__ b3v,
    float* __restrict__ out)
{
    __shared__ float fin[256];
    __shared__ float x1[128];
    __shared__ float x2[64];
    int tid = threadIdx.x;
    int c = blockIdx.x;
    fin[tid] = d_gsum[tid] * (1.0f / (float)NN);
    fin[128 + tid] = d_cfge[c * 128 + tid];
    __syncthreads();
    float a = b1v[tid];
    for (int d = 0; d < 256; d++) a += fin[d] * w1[d * 128 + tid];
    x1[tid] = gelu_f(a);
    __syncthreads();
    if (tid < 64) {
        float a2 = b2v[tid];
        for (int d = 0; d < 128; d++) a2 += x1[d] * w2[d * 64 + tid];
        x2[tid] = gelu_f(a2);
    }
    __syncthreads();
    if (tid == 0) {
        float s = b3v[0];
        for (int d = 0; d < 64; d++) s += x2[d] * w3[d];
        out[c] = s;
    }
}

extern "C" void kernel_launch(void* const* d_in, const int* in_sizes, int n_in,
                              void* d_out, int out_size) {
    const float* node_feat     = (const float*)d_in[0];
    const int*   node_opcode   = (const int*)  d_in[1];
    const float* topo_depth    = (const float*)d_in[2];
    const int*   edge_index    = (const int*)  d_in[3];
    const int*   config_ids    = (const int*)  d_in[4];
    const float* config_feat   = (const float*)d_in[5];
    const float* temperature   = (const float*)d_in[6];
    const float* opcode_embed  = (const float*)d_in[7];
    const float* in_w          = (const float*)d_in[8];
    const float* in_b          = (const float*)d_in[9];
    const float* in_g          = (const float*)d_in[10];
    const float* in_beta       = (const float*)d_in[11];
    const float* sage_Wl       = (const float*)d_in[12];
    const float* sage_bl       = (const float*)d_in[13];
    const float* sage_Wr       = (const float*)d_in[14];
    const float* ln_g          = (const float*)d_in[15];
    const float* ln_b          = (const float*)d_in[16];
    const float* cfg_w         = (const float*)d_in[17];
    const float* cfg_b         = (const float*)d_in[18];
    const float* se_w1         = (const float*)d_in[19];
    const float* se_b1         = (const float*)d_in[20];
    const float* se_w2         = (const float*)d_in[21];
    const float* se_b2         = (const float*)d_in[22];
    const float* h_w1          = (const float*)d_in[23];
    const float* h_b1          = (const float*)d_in[24];
    const float* h_w2          = (const float*)d_in[25];
    const float* h_b2          = (const float*)d_in[26];
    const float* h_w3          = (const float*)d_in[27];
    const float* h_b3          = (const float*)d_in[28];
    float* out = (float*)d_out;

    // CSR build
    zero_ints<<<(NN + 255) / 256, 256>>>();
    degree_kernel<<<(MM + 255) / 256, 256>>>(edge_index);
    scan_kernel<<<1, 1024>>>();
    invdeg_kernel<<<(NN + 255) / 256, 256>>>();
    csr_fill<<<(MM + 255) / 256, 256>>>(edge_index);

    // input embedding + projection
    input_kernel<<<NN / 4, 128>>>(node_feat, node_opcode, topo_depth, opcode_embed,
                                  in_w, in_b, in_g, in_beta);

    // 4 SAGE layers
    for (int l = 0; l < NLAYERS; l++) {
        int flip = l & 1;
        gather_kernel<<<(NN * 32 + 255) / 256, 256>>>(flip);
        conv_kernel<<<(NN + 127) / 128, 256>>>(flip,
                                     sage_Wl + l * HH * HH, sage_bl + l * HH,
                                     sage_Wr + l * HH * HH,
                                     ln_g + l * HH, ln_b + l * HH);
    }

    // global mean
    zero_floats<<<1, 128>>>(2);
    gsum_kernel<<<512, 128>>>();

    // config scoring
    base_kernel<<<NCC, 128>>>(config_ids, cfg_w, cfg_b);
    zero_floats<<<512, 256>>>(3);
    {
        dim3 g(CC / 32, NCC);
        projse_kernel<<<g, 128>>>(config_feat, cfg_w, se_w1, se_b1, se_w2, se_b2);
    }
    {
        dim3 g(HH, 25);
        softmax_kernel<<<g, 512>>>(temperature);
    }
    head_kernel<<<CC, 128>>>(h_w1, h_b1, h_w2, h_b2, h_w3, h_b3, out);
}